// round 1
// baseline (speedup 1.0000x reference)
#include <cuda_runtime.h>
#include <math.h>

// Problem constants (from reference): kv (16,1024,259) f32, positions (16,1024,3) f32
// out (16,1024,3) f32.
#define BATCH     16
#define NN        1024
#define EE        128
#define CC        259          // 2*E + 3 (kv channel stride)
#define TN        128          // n rows per block
#define TM        64           // m tile per iteration
#define VPAD      4
#define VSTRIDE   (TM + VPAD)  // 68 floats: 272B rows -> 16B aligned, conflict-free LDS.128
#define NTHREADS  256
#define INV_SQRT_E 0.0883883476483184406f   // 1/sqrt(128)

#define SMEM_FLOATS (TN*EE + EE*VSTRIDE + TM*3)
#define SMEM_BYTES  (SMEM_FLOATS * 4)

__global__ __launch_bounds__(NTHREADS, 1)
void actor_kernel(const float* __restrict__ kv,
                  const float* __restrict__ pos,
                  float* __restrict__ out)
{
    extern __shared__ float smem[];
    float* k_s  = smem;                 // [TN][EE], prescaled by 1/sqrt(E)
    float* v_s  = smem + TN * EE;       // [EE][VSTRIDE] (e-major, m contiguous)
    float* pm_s = v_s + EE * VSTRIDE;   // [TM][3]

    const int b   = blockIdx.y;
    const int n0  = blockIdx.x * TN;
    const int tid = threadIdx.x;
    const int tx  = tid & 15;           // m-group (4 cols each)
    const int ty  = tid >> 4;           // n-group (8 rows each)

    const float* kvb  = kv  + (size_t)b * NN * CC;
    const float* posb = pos + (size_t)b * NN * 3;

    // ---- load K tile once (coalesced gmem, conflict-free smem stores) ----
    for (int idx = tid; idx < TN * EE; idx += NTHREADS) {
        int r = idx >> 7;           // n local
        int e = idx & 127;
        k_s[r * EE + e] = kvb[(size_t)(n0 + r) * CC + e] * INV_SQRT_E;
    }

    // ---- this thread's n-row positions in registers ----
    float pnx[8], pny[8], pnz[8];
    #pragma unroll
    for (int i = 0; i < 8; i++) {
        int n = n0 + ty * 8 + i;
        pnx[i] = posb[(size_t)n * 3 + 0];
        pny[i] = posb[(size_t)n * 3 + 1];
        pnz[i] = posb[(size_t)n * 3 + 2];
    }

    float accx[8], accy[8], accz[8];
    #pragma unroll
    for (int i = 0; i < 8; i++) { accx[i] = 0.f; accy[i] = 0.f; accz[i] = 0.f; }

    // ================= main loop over m tiles =================
    for (int m0 = 0; m0 < NN; m0 += TM) {
        __syncthreads();   // previous tile fully consumed (also orders k_s on iter 0 with next sync)

        // load V tile transposed into e-major layout (coalesced gmem along e)
        for (int idx = tid; idx < TM * EE; idx += NTHREADS) {
            int r = idx >> 7;       // m local
            int e = idx & 127;
            v_s[e * VSTRIDE + r] = kvb[(size_t)(m0 + r) * CC + EE + e];
        }
        // m-tile positions
        for (int idx = tid; idx < TM * 3; idx += NTHREADS)
            pm_s[idx] = posb[(size_t)m0 * 3 + idx];
        __syncthreads();

        // ---- S subtile: 8 n-rows x 4 m-cols per thread ----
        float S[8][4];
        #pragma unroll
        for (int i = 0; i < 8; i++)
            #pragma unroll
            for (int j = 0; j < 4; j++) S[i][j] = 0.f;

        #pragma unroll 1   // keep body ~2KB for L0 I-cache; inner fully unrolled
        for (int e = 0; e < EE; e += 4) {
            float ka[8][4];
            #pragma unroll
            for (int i = 0; i < 8; i++) {
                float4 t = *(const float4*)(k_s + (ty * 8 + i) * EE + e);
                ka[i][0] = t.x; ka[i][1] = t.y; ka[i][2] = t.z; ka[i][3] = t.w;
            }
            float va[4][4];
            #pragma unroll
            for (int s = 0; s < 4; s++) {
                float4 t = *(const float4*)(v_s + (e + s) * VSTRIDE + tx * 4);
                va[s][0] = t.x; va[s][1] = t.y; va[s][2] = t.z; va[s][3] = t.w;
            }
            #pragma unroll
            for (int i = 0; i < 8; i++)
                #pragma unroll
                for (int s = 0; s < 4; s++)
                    #pragma unroll
                    for (int j = 0; j < 4; j++)
                        S[i][j] = fmaf(ka[i][s], va[s][j], S[i][j]);
        }

        // ---- fused epilogue: geometric weighting, accumulate actions ----
        #pragma unroll
        for (int j = 0; j < 4; j++) {
            int ml = tx * 4 + j;
            float pmx = pm_s[ml * 3 + 0];
            float pmy = pm_s[ml * 3 + 1];
            float pmz = pm_s[ml * 3 + 2];
            #pragma unroll
            for (int i = 0; i < 8; i++) {
                float dx = pnx[i] - pmx;
                float dy = pny[i] - pmy;
                float dz = pnz[i] - pmz;
                // +1e-30 keeps the diagonal finite: dx==0 => contribution 0*huge = 0
                float sq = fmaf(dx, dx, fmaf(dy, dy, fmaf(dz, dz, 1e-30f)));
                float w  = S[i][j] * rsqrtf(sq);
                accx[i] = fmaf(dx, w, accx[i]);
                accy[i] = fmaf(dy, w, accy[i]);
                accz[i] = fmaf(dz, w, accz[i]);
            }
        }
    }

    // ---- reduce the 16 tx-slices (xor-shuffle stays within 16-lane halves) ----
    #pragma unroll
    for (int off = 8; off >= 1; off >>= 1) {
        #pragma unroll
        for (int i = 0; i < 8; i++) {
            accx[i] += __shfl_xor_sync(0xffffffffu, accx[i], off);
            accy[i] += __shfl_xor_sync(0xffffffffu, accy[i], off);
            accz[i] += __shfl_xor_sync(0xffffffffu, accz[i], off);
        }
    }

    if (tx == 0) {
        #pragma unroll
        for (int i = 0; i < 8; i++) {
            int n = n0 + ty * 8 + i;
            float* o = out + ((size_t)b * NN + n) * 3;
            o[0] = 0.01f * tanhf(accx[i]);
            o[1] = 0.01f * tanhf(accy[i]);
            o[2] = 0.01f * tanhf(accz[i]);
        }
    }
}

extern "C" void kernel_launch(void* const* d_in, const int* in_sizes, int n_in,
                              void* d_out, int out_size)
{
    const float* kv  = (const float*)d_in[0];
    const float* pos = (const float*)d_in[1];
    float* out = (float*)d_out;
    (void)in_sizes; (void)n_in; (void)out_size;

    cudaFuncSetAttribute(actor_kernel,
                         cudaFuncAttributeMaxDynamicSharedMemorySize, SMEM_BYTES);

    dim3 grid(NN / TN, BATCH);   // (8, 16) = 128 blocks, one wave on 148 SMs
    actor_kernel<<<grid, NTHREADS, SMEM_BYTES>>>(kv, pos, out);
}